// round 13
// baseline (speedup 1.0000x reference)
#include <cuda_runtime.h>
#include <cuda_bf16.h>
#include <cuda_fp16.h>
#include <cstdint>

#define N_AGENT 25
#define N_S     32
#define BATCH   2048
#define K1      800
#define KP1     832            // 13*64
#define EHH     3200           // 50*64
#define N2      300
#define N2P     320
#define N_EDGE  300
#define KSPLIT2 3

#define ROWB    144

// ---- mm1 smem layout (128x128 tile): A hi+lo (fp16), B hi only (fp16) ----
#define M1_AHI  0
#define M1_ALO  18432
#define M1_BHI  36864
#define M1_BUF  55296
#define M1_TOT  (2 * M1_BUF)
// ---- mm2 smem layout (128x64): A 128 rows hi+lo, B 64 rows hi+lo (bf16) ----
#define M2_AHI  0
#define M2_ALO  18432
#define M2_BHI  36864
#define M2_BLO  46080
#define M2_BUF  55296
#define M2_TOT  (2 * M2_BUF)

// ---- device scratch ----
__device__ float g_mu[K1];
__device__ float g_rstd[K1];
__device__ int   g_wtag[EHH];
__device__ __half g_Ahi[(size_t)BATCH * KP1];
__device__ __half g_Alo[(size_t)BATCH * KP1];
__device__ __half g_Bthi[(size_t)EHH * KP1];
__device__ __nv_bfloat16 g_Ehi[(size_t)BATCH * EHH];
__device__ __nv_bfloat16 g_Elo[(size_t)BATCH * EHH];
__device__ __nv_bfloat16 g_W1thi[(size_t)N2P * EHH];
__device__ __nv_bfloat16 g_W1tlo[(size_t)N2P * EHH];
__device__ float g_h1p[(size_t)KSPLIT2 * BATCH * N2P];

__device__ __forceinline__ float leaky(float x) { return x >= 0.f ? x : 0.01f * x; }
__device__ __forceinline__ void bf16split(float x, __nv_bfloat16& h, __nv_bfloat16& l) {
    h = __float2bfloat16(x);
    l = __float2bfloat16(x - __bfloat162float(h));
}
__device__ __forceinline__ void f16split(float x, __half& h, __half& l) {
    h = __float2half_rn(x);
    l = __float2half_rn(x - __half2float(h));
}
__device__ __forceinline__ uint32_t smem_u32(const void* p) {
    uint32_t a;
    asm("{ .reg .u64 t; cvta.to.shared.u64 t, %1; cvt.u32.u64 %0, t; }" : "=r"(a) : "l"(p));
    return a;
}
__device__ __forceinline__ uint32_t packbf2(float x, float y) {
    __nv_bfloat162 t = __floats2bfloat162_rn(x, y);
    return *(uint32_t*)&t;
}

#define CP16(dst, src) asm volatile("cp.async.cg.shared.global [%0], [%1], 16;" :: "r"(dst), "l"(src))
#define CP_COMMIT()    asm volatile("cp.async.commit_group;")
#define CP_WAIT0()     asm volatile("cp.async.wait_group 0;")
#define CP_WAIT1()     asm volatile("cp.async.wait_group 1;")
#define LDM4(r, addr)  asm volatile("ldmatrix.sync.aligned.m8n8.x4.shared.b16 {%0,%1,%2,%3}, [%4];" \
    : "=r"((r)[0]), "=r"((r)[1]), "=r"((r)[2]), "=r"((r)[3]) : "r"(addr))

__device__ __forceinline__ void mmabf(float* c, const uint32_t* a, uint32_t b0, uint32_t b1) {
    asm volatile(
        "mma.sync.aligned.m16n8k16.row.col.f32.bf16.bf16.f32 "
        "{%0,%1,%2,%3},{%4,%5,%6,%7},{%8,%9},{%0,%1,%2,%3};"
        : "+f"(c[0]), "+f"(c[1]), "+f"(c[2]), "+f"(c[3])
        : "r"(a[0]), "r"(a[1]), "r"(a[2]), "r"(a[3]), "r"(b0), "r"(b1));
}
__device__ __forceinline__ void mmaf16(float* c, const uint32_t* a, uint32_t b0, uint32_t b1) {
    asm volatile(
        "mma.sync.aligned.m16n8k16.row.col.f32.f16.f16.f32 "
        "{%0,%1,%2,%3},{%4,%5,%6,%7},{%8,%9},{%0,%1,%2,%3};"
        : "+f"(c[0]), "+f"(c[1]), "+f"(c[2]), "+f"(c[3])
        : "r"(a[0]), "r"(a[1]), "r"(a[2]), "r"(a[3]), "r"(b0), "r"(b1));
}

// ============================================================
// 1) batch-norm stats (coalesced: block = agent, lane = feature)
// ============================================================
__global__ void k_stats(const float* __restrict__ states) {
    int a = blockIdx.x;
    int w = threadIdx.x >> 5, lane = threadIdx.x & 31;
    float sum = 0.f, sq = 0.f;
    const float* base = states + (size_t)a * BATCH * N_S + lane;
    for (int b = w; b < BATCH; b += 8) {
        float v = base[(size_t)b * N_S];
        sum += v; sq += v * v;
    }
    __shared__ float ss[8][32], qq[8][32];
    ss[w][lane] = sum; qq[w][lane] = sq;
    __syncthreads();
    if (w == 0) {
        float S = 0.f, Q = 0.f;
        #pragma unroll
        for (int i = 0; i < 8; i++) { S += ss[i][lane]; Q += qq[i][lane]; }
        float mu  = S * (1.f / BATCH);
        float var = Q * (1.f / BATCH) - mu * mu;
        g_mu[a * 32 + lane]   = mu;
        g_rstd[a * 32 + lane] = rsqrtf(var + 1e-5f);
    }
}

// ============================================================
// 2) winner tags via priority atomicMax (== sequential last-write-wins)
//    512 threads (covers all 300 edges)
// ============================================================
__global__ void k_winner(const int* __restrict__ adj) {
    int t = threadIdx.x;
    for (int i = t; i < EHH; i += 512) g_wtag[i] = -1;
    __syncthreads();
    if (t < N_EDGE) {
        int r1  = adj[t * 4 + 1];
        int r3  = adj[t * 4 + 3];
        int src = adj[t * 4 + 0];
        atomicMax(&g_wtag[r1], (t << 16) | src);
        atomicMax(&g_wtag[r3], ((t + N_EDGE) << 16) | src);
    }
}

// ============================================================
// 3) W1eff^T bf16 hi/lo: [320 n][3200 k]; coalesced w1 reads
// ============================================================
__global__ void k_w1t(const float* __restrict__ anova, const float* __restrict__ w1) {
    int a  = blockIdx.x;
    int kb = blockIdx.y * 128;
    int t  = threadIdx.x;
    if (a == N_AGENT) {           // zero rows 300..319
        for (int idx = t; idx < 20 * 64; idx += 256) {
            int n = N2 + idx / 64, kp = idx % 64;
            *(uint32_t*)(g_W1thi + (size_t)n * EHH + kb + kp * 2) = 0u;
            *(uint32_t*)(g_W1tlo + (size_t)n * EHH + kb + kp * 2) = 0u;
        }
        return;
    }
    __shared__ float att_s[128];
    __shared__ __nv_bfloat16 oh[12][128], ol[12][128];
    if (t < 128) {
        int k = kb + t;
        int tag = g_wtag[k];
        float neigh = (tag >= 0) ? anova[(size_t)(EHH + (tag & 0xFFFF)) * N_AGENT + a] : 0.f;
        att_s[t] = anova[(size_t)k * N_AGENT + a] + neigh;
    }
    __syncthreads();
    #pragma unroll
    for (int r = 0; r < 6; r++) {
        int idx = t + 256 * r;          // 0..1535
        int k = idx / 12, kk = idx % 12;
        float v = att_s[k] * w1[((size_t)a * EHH + kb + k) * 12 + kk];
        __nv_bfloat16 h, l; bf16split(v, h, l);
        oh[kk][k] = h; ol[kk][k] = l;
    }
    __syncthreads();
    #pragma unroll
    for (int r = 0; r < 3; r++) {
        int idx = t + 256 * r;          // 0..767 (u32 pairs)
        int kk = idx / 64, kp = idx % 64;
        int n = a * 12 + kk;
        *(uint32_t*)(g_W1thi + (size_t)n * EHH + kb + kp * 2) = *(uint32_t*)&oh[kk][kp * 2];
        *(uint32_t*)(g_W1tlo + (size_t)n * EHH + kb + kp * 2) = *(uint32_t*)&ol[kk][kp * 2];
    }
}

// ============================================================
// 4) A prep: normalized states -> fp16 hi/lo [2048][832]
// ============================================================
__global__ void k_aprep(const float* __restrict__ states) {
    int b = blockIdx.x;
    for (int k = threadIdx.x; k < KP1; k += 256) {
        float x = 0.f;
        if (k < K1) {
            int a = k >> 5, s = k & 31;
            x = (states[((size_t)a * BATCH + b) * N_S + s] - g_mu[k]) * g_rstd[k];
        }
        __half h, l; f16split(x, h, l);
        g_Ahi[(size_t)b * KP1 + k] = h;
        g_Alo[(size_t)b * KP1 + k] = l;
    }
}

// ============================================================
// 5) B prep: transpose ehh_w [800][3200] -> Bt fp16 (hi only) [3200][832]
// ============================================================
__global__ void k_btrans(const float* __restrict__ ehh_w) {
    __shared__ float tl[32][33];
    int n0 = blockIdx.x * 32;
    int k0 = blockIdx.y * 32;
    int tx = threadIdx.x, ty = threadIdx.y;   // 32 x 8
    #pragma unroll
    for (int i = 0; i < 4; i++) {
        int kr = ty + 8 * i;
        int kg = k0 + kr;
        tl[kr][tx] = (kg < K1) ? ehh_w[(size_t)kg * EHH + n0 + tx] : 0.f;
    }
    __syncthreads();
    #pragma unroll
    for (int i = 0; i < 4; i++) {
        int nr = ty + 8 * i;
        g_Bthi[(size_t)(n0 + nr) * KP1 + k0 + tx] = __float2half_rn(tl[tx][nr]);
    }
}

// ============================================================
// 6) GEMM1 HMMA fp16 2-term: emb = leaky(Anorm @ ehh_w)
//    A = Ah + Al (fp16, exact), B = fp16(ehh_w)  =>  Ah*B + Al*B
//    block tile 128(m) x 128(n), warp tile 32x64, 13 K-chunks of 64
// ============================================================
__global__ void __launch_bounds__(256) k_mm1() {
    extern __shared__ __align__(16) char smem[];
    uint32_t sb = smem_u32(smem);
    int tid = threadIdx.x;
    int wid = tid >> 5, lid = tid & 31;
    int wm = wid & 3, wn = wid >> 2;
    int trow = lid & 7, th = lid >> 3;
    int m0 = blockIdx.y * 128, n0 = blockIdx.x * 128;

    uint32_t aOff[2], bOff[4];
    #pragma unroll
    for (int i = 0; i < 2; i++)
        aOff[i] = (uint32_t)((wm * 32 + i * 16 + trow + ((th & 1) << 3)) * ROWB + ((th >> 1) << 4));
    #pragma unroll
    for (int j = 0; j < 4; j++)
        bOff[j] = (uint32_t)((wn * 64 + j * 16 + trow + ((th >> 1) << 3)) * ROWB + ((th & 1) << 4));

    float acc[2][8][4];
    #pragma unroll
    for (int i = 0; i < 2; i++)
        #pragma unroll
        for (int j = 0; j < 8; j++)
            #pragma unroll
            for (int r = 0; r < 4; r++) acc[i][j][r] = 0.f;

    #define STAGE1(buf, c) do {                                                         \
        uint32_t base = sb + (buf) * M1_BUF;                                            \
        size_t col = (size_t)(c) * 64;                                                  \
        _Pragma("unroll")                                                               \
        for (int j = 0; j < 4; j++) {                                                   \
            int lin = tid + 256 * j;                                                    \
            int row = lin >> 3, u = lin & 7;                                            \
            uint32_t d = base + row * ROWB + u * 16;                                    \
            CP16(d + M1_AHI, g_Ahi  + (size_t)(m0 + row) * KP1 + col + u * 8);          \
            CP16(d + M1_ALO, g_Alo  + (size_t)(m0 + row) * KP1 + col + u * 8);          \
            CP16(d + M1_BHI, g_Bthi + (size_t)(n0 + row) * KP1 + col + u * 8);          \
        }                                                                               \
    } while (0)

    STAGE1(0, 0);
    CP_COMMIT();
    for (int c = 0; c < 13; c++) {
        if (c + 1 < 13) { STAGE1((c + 1) & 1, c + 1); CP_COMMIT(); CP_WAIT1(); }
        else CP_WAIT0();
        __syncthreads();
        uint32_t base = sb + (c & 1) * M1_BUF;
        #pragma unroll
        for (int ks = 0; ks < 4; ks++) {
            uint32_t ah[2][4], al[2][4], bh[4][4];
            #pragma unroll
            for (int i = 0; i < 2; i++) {
                LDM4(ah[i], base + M1_AHI + aOff[i] + ks * 32);
                LDM4(al[i], base + M1_ALO + aOff[i] + ks * 32);
            }
            #pragma unroll
            for (int j = 0; j < 4; j++)
                LDM4(bh[j], base + M1_BHI + bOff[j] + ks * 32);
            #pragma unroll
            for (int i = 0; i < 2; i++)
                #pragma unroll
                for (int jj = 0; jj < 8; jj++) {
                    float* cc = acc[i][jj];
                    uint32_t h0 = bh[jj >> 1][(jj & 1) * 2], h1 = bh[jj >> 1][(jj & 1) * 2 + 1];
                    mmaf16(cc, ah[i], h0, h1);
                    mmaf16(cc, al[i], h0, h1);
                }
        }
        __syncthreads();
    }
    #undef STAGE1

    // epilogue: leaky + bf16 hi/lo split (emb feeds bf16x3 mm2)
    int gid = lid >> 2, tid4 = lid & 3;
    #pragma unroll
    for (int i = 0; i < 2; i++) {
        #pragma unroll
        for (int jj = 0; jj < 8; jj++) {
            int col = n0 + wn * 64 + jj * 8 + tid4 * 2;
            int r0  = m0 + wm * 32 + i * 16 + gid;
            float v0 = leaky(acc[i][jj][0]), v1 = leaky(acc[i][jj][1]);
            float v2 = leaky(acc[i][jj][2]), v3 = leaky(acc[i][jj][3]);
            __nv_bfloat16 h0, l0, h1, l1, h2, l2, h3, l3;
            bf16split(v0, h0, l0); bf16split(v1, h1, l1);
            bf16split(v2, h2, l2); bf16split(v3, h3, l3);
            *(uint32_t*)(g_Ehi + (size_t)r0 * EHH + col)       = packbf2(__bfloat162float(h0), __bfloat162float(h1));
            *(uint32_t*)(g_Elo + (size_t)r0 * EHH + col)       = packbf2(__bfloat162float(l0), __bfloat162float(l1));
            *(uint32_t*)(g_Ehi + (size_t)(r0 + 8) * EHH + col) = packbf2(__bfloat162float(h2), __bfloat162float(h3));
            *(uint32_t*)(g_Elo + (size_t)(r0 + 8) * EHH + col) = packbf2(__bfloat162float(l2), __bfloat162float(l3));
        }
    }
}

// ============================================================
// 7) GEMM2 HMMA: h1 partials = emb @ W1eff (bf16x3, split-K=3)
//    block tile 128 x 64; chunks 17/17/16 of K=64
// ============================================================
__global__ void __launch_bounds__(256) k_mm2() {
    extern __shared__ __align__(16) char smem[];
    uint32_t sb = smem_u32(smem);
    int tid = threadIdx.x;
    int wid = tid >> 5, lid = tid & 31;
    int wm = wid >> 1, wn = wid & 1;
    int trow = lid & 7, th = lid >> 3;
    int n0 = blockIdx.x * 64, m0 = blockIdx.y * 128;
    int ks2 = blockIdx.z;
    int cstart = ks2 * 17;
    int nch = (ks2 == 2) ? 16 : 17;

    uint32_t aOff[2], bOff[2];
    #pragma unroll
    for (int i = 0; i < 2; i++)
        aOff[i] = (uint32_t)((wm * 32 + i * 16 + trow + ((th & 1) << 3)) * ROWB + ((th >> 1) << 4));
    #pragma unroll
    for (int j = 0; j < 2; j++)
        bOff[j] = (uint32_t)((wn * 32 + j * 16 + trow + ((th >> 1) << 3)) * ROWB + ((th & 1) << 4));

    float acc[2][4][4];
    #pragma unroll
    for (int i = 0; i < 2; i++)
        #pragma unroll
        for (int j = 0; j < 4; j++)
            #pragma unroll
            for (int r = 0; r < 4; r++) acc[i][j][r] = 0.f;

    #define STAGE2(buf, c) do {                                                         \
        uint32_t base = sb + (buf) * M2_BUF;                                            \
        size_t col = (size_t)(cstart + (c)) * 64;                                       \
        _Pragma("unroll")                                                               \
        for (int j = 0; j < 4; j++) {                                                   \
            int lin = tid + 256 * j;                                                    \
            int row = lin >> 3, u = lin & 7;                                            \
            uint32_t d = base + row * ROWB + u * 16;                                    \
            CP16(d + M2_AHI, g_Ehi + (size_t)(m0 + row) * EHH + col + u * 8);           \
            CP16(d + M2_ALO, g_Elo + (size_t)(m0 + row) * EHH + col + u * 8);           \
        }                                                                               \
        _Pragma("unroll")                                                               \
        for (int j = 0; j < 2; j++) {                                                   \
            int lin = tid + 256 * j;                                                    \
            int row = lin >> 3, u = lin & 7;                                            \
            uint32_t d = base + row * ROWB + u * 16;                                    \
            CP16(d + M2_BHI, g_W1thi + (size_t)(n0 + row) * EHH + col + u * 8);         \
            CP16(d + M2_BLO, g_W1tlo + (size_t)(n0 + row) * EHH + col + u * 8);         \
        }                                                                               \
    } while (0)

    STAGE2(0, 0);
    CP_COMMIT();
    for (int c = 0; c < nch; c++) {
        if (c + 1 < nch) { STAGE2((c + 1) & 1, c + 1); CP_COMMIT(); CP_WAIT1(); }
        else CP_WAIT0();
        __syncthreads();
        uint32_t base = sb + (c & 1) * M2_BUF;
        #pragma unroll
        for (int ks = 0; ks < 4; ks++) {
            uint32_t ah[2][4], al[2][4], bh[2][4], bl[2][4];
            #pragma unroll
            for (int i = 0; i < 2; i++) {
                LDM4(ah[i], base + M2_AHI + aOff[i] + ks * 32);
                LDM4(al[i], base + M2_ALO + aOff[i] + ks * 32);
            }
            #pragma unroll
            for (int j = 0; j < 2; j++) {
                LDM4(bh[j], base + M2_BHI + bOff[j] + ks * 32);
                LDM4(bl[j], base + M2_BLO + bOff[j] + ks * 32);
            }
            #pragma unroll
            for (int i = 0; i < 2; i++)
                #pragma unroll
                for (int jj = 0; jj < 4; jj++) {
                    float* cc = acc[i][jj];
                    uint32_t h0 = bh[jj >> 1][(jj & 1) * 2], h1 = bh[jj >> 1][(jj & 1) * 2 + 1];
                    uint32_t l0 = bl[jj >> 1][(jj & 1) * 2], l1 = bl[jj >> 1][(jj & 1) * 2 + 1];
                    mmabf(cc, ah[i], h0, h1);
                    mmabf(cc, al[i], h0, h1);
                    mmabf(cc, ah[i], l0, l1);
                }
        }
        __syncthreads();
    }
    #undef STAGE2

    int gid = lid >> 2, tid4 = lid & 3;
    #pragma unroll
    for (int i = 0; i < 2; i++) {
        #pragma unroll
        for (int jj = 0; jj < 4; jj++) {
            int col = n0 + wn * 32 + jj * 8 + tid4 * 2;
            int r0  = m0 + wm * 32 + i * 16 + gid;
            float2 lo = {acc[i][jj][0], acc[i][jj][1]};
            float2 hi = {acc[i][jj][2], acc[i][jj][3]};
            *(float2*)&g_h1p[((size_t)ks2 * BATCH + r0) * N2P + col]     = lo;
            *(float2*)&g_h1p[((size_t)ks2 * BATCH + r0 + 8) * N2P + col] = hi;
        }
    }
}

// ============================================================
// 8) reduce split-K + bias + leaky + tiny MLP + gather
// ============================================================
__global__ void k_tail(const float* __restrict__ b1, const float* __restrict__ w2,
                       const float* __restrict__ b2, const float* __restrict__ w3,
                       const float* __restrict__ b3, const int* __restrict__ actions,
                       float* __restrict__ out) {
    __shared__ float w2s[144], w3s[48], b2s[12], b3s[4], b1s[12];
    int a = blockIdx.y;
    int t = threadIdx.x;
    for (int i = t; i < 144; i += 128) w2s[i] = w2[a * 144 + i];
    if (t < 48)  w3s[t] = w3[a * 48 + t];
    if (t < 12)  { b2s[t] = b2[a * 12 + t]; b1s[t] = b1[a * 12 + t]; }
    if (t < 4)   b3s[t] = b3[a * 4 + t];
    __syncthreads();
    int b = blockIdx.x * 128 + t;
    float x[12] = {0,0,0,0,0,0,0,0,0,0,0,0};
    #pragma unroll
    for (int ks = 0; ks < KSPLIT2; ks++) {
        const float4* p = (const float4*)&g_h1p[((size_t)ks * BATCH + b) * N2P + a * 12];
        float4 q0 = p[0], q1 = p[1], q2 = p[2];
        x[0] += q0.x; x[1] += q0.y; x[2]  += q0.z; x[3]  += q0.w;
        x[4] += q1.x; x[5] += q1.y; x[6]  += q1.z; x[7]  += q1.w;
        x[8] += q2.x; x[9] += q2.y; x[10] += q2.z; x[11] += q2.w;
    }
    #pragma unroll
    for (int k = 0; k < 12; k++) x[k] = leaky(x[k] + b1s[k]);
    int act = actions[(size_t)a * BATCH + b];
    float q = b3s[act];
    #pragma unroll
    for (int j = 0; j < 12; j++) {
        float s = b2s[j];
        #pragma unroll
        for (int k = 0; k < 12; k++) s += x[k] * w2s[k * 12 + j];
        q += leaky(s) * w3s[j * 4 + act];
    }
    out[(size_t)a * BATCH + b] = q;
}

// ============================================================
extern "C" void kernel_launch(void* const* d_in, const int* in_sizes, int n_in,
                              void* d_out, int out_size) {
    const float* states = (const float*)d_in[0];
    const float* ehh_w  = (const float*)d_in[1];
    const float* anova  = (const float*)d_in[2];
    const float* w1     = (const float*)d_in[3];
    const float* b1     = (const float*)d_in[4];
    const float* w2     = (const float*)d_in[5];
    const float* b2     = (const float*)d_in[6];
    const float* w3     = (const float*)d_in[7];
    const float* b3     = (const float*)d_in[8];
    const int* actions  = (const int*)d_in[9];
    const int* adj      = (const int*)d_in[10];
    float* out = (float*)d_out;

    cudaFuncSetAttribute(k_mm1, cudaFuncAttributeMaxDynamicSharedMemorySize, M1_TOT);
    cudaFuncSetAttribute(k_mm2, cudaFuncAttributeMaxDynamicSharedMemorySize, M2_TOT);

    // order chosen so k_mm1 is the 4th launch (ncu capture slot)
    k_stats  <<<N_AGENT, 256>>>(states);
    k_aprep  <<<BATCH, 256>>>(states);
    k_btrans <<<dim3(EHH / 32, KP1 / 32), dim3(32, 8)>>>(ehh_w);
    k_mm1    <<<dim3(EHH / 128, BATCH / 128), 256, M1_TOT>>>();
    k_winner <<<1, 512>>>(adj);
    k_w1t    <<<dim3(N_AGENT + 1, EHH / 128), 256>>>(anova, w1);
    k_mm2    <<<dim3(N2P / 64, BATCH / 128, KSPLIT2), 256, M2_TOT>>>();
    k_tail   <<<dim3(BATCH / 128, N_AGENT), 128>>>(b1, w2, b2, w3, b3, actions, out);
}

// round 14
// speedup vs baseline: 1.0628x; 1.0628x over previous
#include <cuda_runtime.h>
#include <cuda_bf16.h>
#include <cuda_fp16.h>
#include <cstdint>

#define N_AGENT 25
#define N_S     32
#define BATCH   2048
#define K1      800
#define KP1     832            // 13*64
#define EHH     3200           // 50*64
#define N2      300
#define N2P     320
#define N_EDGE  300
#define KSPLIT2 3

#define ROWB    144

// ---- mm1 smem layout (128x128 tile): A hi+lo (fp16), B hi only (fp16) ----
#define M1_AHI  0
#define M1_ALO  18432
#define M1_BHI  36864
#define M1_BUF  55296
#define M1_TOT  (2 * M1_BUF)
// ---- mm2 smem layout (128x64): A 128 rows hi+lo, B 64 rows hi+lo (fp16) ----
#define M2_AHI  0
#define M2_ALO  18432
#define M2_BHI  36864
#define M2_BLO  46080
#define M2_BUF  55296
#define M2_TOT  (2 * M2_BUF)

// ---- device scratch ----
__device__ float g_mu[K1];
__device__ float g_rstd[K1];
__device__ int   g_wtag[EHH];
__device__ __half g_Ahi[(size_t)BATCH * KP1];
__device__ __half g_Alo[(size_t)BATCH * KP1];
__device__ __half g_Bthi[(size_t)EHH * KP1];
__device__ __half g_Ehi[(size_t)BATCH * EHH];
__device__ __half g_Elo[(size_t)BATCH * EHH];
__device__ __half g_W1thi[(size_t)N2P * EHH];
__device__ __half g_W1tlo[(size_t)N2P * EHH];
__device__ float g_h1p[(size_t)KSPLIT2 * BATCH * N2P];

__device__ __forceinline__ float leaky(float x) { return x >= 0.f ? x : 0.01f * x; }
__device__ __forceinline__ void f16split(float x, __half& h, __half& l) {
    h = __float2half_rn(x);
    l = __float2half_rn(x - __half2float(h));
}
__device__ __forceinline__ uint32_t smem_u32(const void* p) {
    uint32_t a;
    asm("{ .reg .u64 t; cvta.to.shared.u64 t, %1; cvt.u32.u64 %0, t; }" : "=r"(a) : "l"(p));
    return a;
}
__device__ __forceinline__ uint32_t packh2(float x, float y) {
    __half2 t = __floats2half2_rn(x, y);
    return *(uint32_t*)&t;
}

#define CP16(dst, src) asm volatile("cp.async.cg.shared.global [%0], [%1], 16;" :: "r"(dst), "l"(src))
#define CP_COMMIT()    asm volatile("cp.async.commit_group;")
#define CP_WAIT0()     asm volatile("cp.async.wait_group 0;")
#define CP_WAIT1()     asm volatile("cp.async.wait_group 1;")
#define LDM4(r, addr)  asm volatile("ldmatrix.sync.aligned.m8n8.x4.shared.b16 {%0,%1,%2,%3}, [%4];" \
    : "=r"((r)[0]), "=r"((r)[1]), "=r"((r)[2]), "=r"((r)[3]) : "r"(addr))

__device__ __forceinline__ void mmaf16(float* c, const uint32_t* a, uint32_t b0, uint32_t b1) {
    asm volatile(
        "mma.sync.aligned.m16n8k16.row.col.f32.f16.f16.f32 "
        "{%0,%1,%2,%3},{%4,%5,%6,%7},{%8,%9},{%0,%1,%2,%3};"
        : "+f"(c[0]), "+f"(c[1]), "+f"(c[2]), "+f"(c[3])
        : "r"(a[0]), "r"(a[1]), "r"(a[2]), "r"(a[3]), "r"(b0), "r"(b1));
}

// ============================================================
// 1) batch-norm stats (coalesced: block = agent, lane = feature)
// ============================================================
__global__ void k_stats(const float* __restrict__ states) {
    int a = blockIdx.x;
    int w = threadIdx.x >> 5, lane = threadIdx.x & 31;
    float sum = 0.f, sq = 0.f;
    const float* base = states + (size_t)a * BATCH * N_S + lane;
    for (int b = w; b < BATCH; b += 8) {
        float v = base[(size_t)b * N_S];
        sum += v; sq += v * v;
    }
    __shared__ float ss[8][32], qq[8][32];
    ss[w][lane] = sum; qq[w][lane] = sq;
    __syncthreads();
    if (w == 0) {
        float S = 0.f, Q = 0.f;
        #pragma unroll
        for (int i = 0; i < 8; i++) { S += ss[i][lane]; Q += qq[i][lane]; }
        float mu  = S * (1.f / BATCH);
        float var = Q * (1.f / BATCH) - mu * mu;
        g_mu[a * 32 + lane]   = mu;
        g_rstd[a * 32 + lane] = rsqrtf(var + 1e-5f);
    }
}

// ============================================================
// 2) winner tags via priority atomicMax (== sequential last-write-wins)
// ============================================================
__global__ void k_winner(const int* __restrict__ adj) {
    int t = threadIdx.x;
    for (int i = t; i < EHH; i += 512) g_wtag[i] = -1;
    __syncthreads();
    if (t < N_EDGE) {
        int r1  = adj[t * 4 + 1];
        int r3  = adj[t * 4 + 3];
        int src = adj[t * 4 + 0];
        atomicMax(&g_wtag[r1], (t << 16) | src);
        atomicMax(&g_wtag[r3], ((t + N_EDGE) << 16) | src);
    }
}

// ============================================================
// 3) W1eff^T fp16 hi/lo: [320 n][3200 k]; coalesced w1 reads
// ============================================================
__global__ void k_w1t(const float* __restrict__ anova, const float* __restrict__ w1) {
    int a  = blockIdx.x;
    int kb = blockIdx.y * 128;
    int t  = threadIdx.x;
    if (a == N_AGENT) {           // zero rows 300..319
        for (int idx = t; idx < 20 * 64; idx += 256) {
            int n = N2 + idx / 64, kp = idx % 64;
            *(uint32_t*)(g_W1thi + (size_t)n * EHH + kb + kp * 2) = 0u;
            *(uint32_t*)(g_W1tlo + (size_t)n * EHH + kb + kp * 2) = 0u;
        }
        return;
    }
    __shared__ float att_s[128];
    __shared__ __half oh[12][128], ol[12][128];
    if (t < 128) {
        int k = kb + t;
        int tag = g_wtag[k];
        float neigh = (tag >= 0) ? anova[(size_t)(EHH + (tag & 0xFFFF)) * N_AGENT + a] : 0.f;
        att_s[t] = anova[(size_t)k * N_AGENT + a] + neigh;
    }
    __syncthreads();
    #pragma unroll
    for (int r = 0; r < 6; r++) {
        int idx = t + 256 * r;          // 0..1535
        int k = idx / 12, kk = idx % 12;
        float v = att_s[k] * w1[((size_t)a * EHH + kb + k) * 12 + kk];
        __half h, l; f16split(v, h, l);
        oh[kk][k] = h; ol[kk][k] = l;
    }
    __syncthreads();
    #pragma unroll
    for (int r = 0; r < 3; r++) {
        int idx = t + 256 * r;          // 0..767 (u32 pairs)
        int kk = idx / 64, kp = idx % 64;
        int n = a * 12 + kk;
        *(uint32_t*)(g_W1thi + (size_t)n * EHH + kb + kp * 2) = *(uint32_t*)&oh[kk][kp * 2];
        *(uint32_t*)(g_W1tlo + (size_t)n * EHH + kb + kp * 2) = *(uint32_t*)&ol[kk][kp * 2];
    }
}

// ============================================================
// 4) A prep: normalized states -> fp16 hi/lo [2048][832]
// ============================================================
__global__ void k_aprep(const float* __restrict__ states) {
    int b = blockIdx.x;
    for (int k = threadIdx.x; k < KP1; k += 256) {
        float x = 0.f;
        if (k < K1) {
            int a = k >> 5, s = k & 31;
            x = (states[((size_t)a * BATCH + b) * N_S + s] - g_mu[k]) * g_rstd[k];
        }
        __half h, l; f16split(x, h, l);
        g_Ahi[(size_t)b * KP1 + k] = h;
        g_Alo[(size_t)b * KP1 + k] = l;
    }
}

// ============================================================
// 5) B prep: transpose ehh_w [800][3200] -> Bt fp16 (hi only) [3200][832]
// ============================================================
__global__ void k_btrans(const float* __restrict__ ehh_w) {
    __shared__ float tl[32][33];
    int n0 = blockIdx.x * 32;
    int k0 = blockIdx.y * 32;
    int tx = threadIdx.x, ty = threadIdx.y;   // 32 x 8
    #pragma unroll
    for (int i = 0; i < 4; i++) {
        int kr = ty + 8 * i;
        int kg = k0 + kr;
        tl[kr][tx] = (kg < K1) ? ehh_w[(size_t)kg * EHH + n0 + tx] : 0.f;
    }
    __syncthreads();
    #pragma unroll
    for (int i = 0; i < 4; i++) {
        int nr = ty + 8 * i;
        g_Bthi[(size_t)(n0 + nr) * KP1 + k0 + tx] = __float2half_rn(tl[tx][nr]);
    }
}

// ============================================================
// 6) GEMM1 HMMA fp16 2-term: emb = leaky(Anorm @ ehh_w)
//    block tile 128x128, warp tile 32x64, 13 K-chunks of 64, 2 CTA/SM
// ============================================================
__global__ void __launch_bounds__(256, 2) k_mm1() {
    extern __shared__ __align__(16) char smem[];
    uint32_t sb = smem_u32(smem);
    int tid = threadIdx.x;
    int wid = tid >> 5, lid = tid & 31;
    int wm = wid & 3, wn = wid >> 2;
    int trow = lid & 7, th = lid >> 3;
    int m0 = blockIdx.y * 128, n0 = blockIdx.x * 128;

    uint32_t aOff[2], bOff[4];
    #pragma unroll
    for (int i = 0; i < 2; i++)
        aOff[i] = (uint32_t)((wm * 32 + i * 16 + trow + ((th & 1) << 3)) * ROWB + ((th >> 1) << 4));
    #pragma unroll
    for (int j = 0; j < 4; j++)
        bOff[j] = (uint32_t)((wn * 64 + j * 16 + trow + ((th >> 1) << 3)) * ROWB + ((th & 1) << 4));

    float acc[2][8][4];
    #pragma unroll
    for (int i = 0; i < 2; i++)
        #pragma unroll
        for (int j = 0; j < 8; j++)
            #pragma unroll
            for (int r = 0; r < 4; r++) acc[i][j][r] = 0.f;

    #define STAGE1(buf, c) do {                                                         \
        uint32_t base = sb + (buf) * M1_BUF;                                            \
        size_t col = (size_t)(c) * 64;                                                  \
        _Pragma("unroll")                                                               \
        for (int j = 0; j < 4; j++) {                                                   \
            int lin = tid + 256 * j;                                                    \
            int row = lin >> 3, u = lin & 7;                                            \
            uint32_t d = base + row * ROWB + u * 16;                                    \
            CP16(d + M1_AHI, g_Ahi  + (size_t)(m0 + row) * KP1 + col + u * 8);          \
            CP16(d + M1_ALO, g_Alo  + (size_t)(m0 + row) * KP1 + col + u * 8);          \
            CP16(d + M1_BHI, g_Bthi + (size_t)(n0 + row) * KP1 + col + u * 8);          \
        }                                                                               \
    } while (0)

    STAGE1(0, 0);
    CP_COMMIT();
    for (int c = 0; c < 13; c++) {
        if (c + 1 < 13) { STAGE1((c + 1) & 1, c + 1); CP_COMMIT(); CP_WAIT1(); }
        else CP_WAIT0();
        __syncthreads();
        uint32_t base = sb + (c & 1) * M1_BUF;
        #pragma unroll
        for (int ks = 0; ks < 4; ks++) {
            uint32_t ah[2][4], al[2][4], bh[4][4];
            #pragma unroll
            for (int i = 0; i < 2; i++) {
                LDM4(ah[i], base + M1_AHI + aOff[i] + ks * 32);
                LDM4(al[i], base + M1_ALO + aOff[i] + ks * 32);
            }
            #pragma unroll
            for (int j = 0; j < 4; j++)
                LDM4(bh[j], base + M1_BHI + bOff[j] + ks * 32);
            #pragma unroll
            for (int i = 0; i < 2; i++)
                #pragma unroll
                for (int jj = 0; jj < 8; jj++) {
                    float* cc = acc[i][jj];
                    uint32_t h0 = bh[jj >> 1][(jj & 1) * 2], h1 = bh[jj >> 1][(jj & 1) * 2 + 1];
                    mmaf16(cc, ah[i], h0, h1);
                    mmaf16(cc, al[i], h0, h1);
                }
        }
        __syncthreads();
    }
    #undef STAGE1

    // epilogue: leaky + fp16 hi/lo split (emb feeds fp16x3 mm2)
    int gid = lid >> 2, tid4 = lid & 3;
    #pragma unroll
    for (int i = 0; i < 2; i++) {
        #pragma unroll
        for (int jj = 0; jj < 8; jj++) {
            int col = n0 + wn * 64 + jj * 8 + tid4 * 2;
            int r0  = m0 + wm * 32 + i * 16 + gid;
            float v0 = leaky(acc[i][jj][0]), v1 = leaky(acc[i][jj][1]);
            float v2 = leaky(acc[i][jj][2]), v3 = leaky(acc[i][jj][3]);
            __half h0, l0, h1, l1, h2, l2, h3, l3;
            f16split(v0, h0, l0); f16split(v1, h1, l1);
            f16split(v2, h2, l2); f16split(v3, h3, l3);
            *(uint32_t*)(g_Ehi + (size_t)r0 * EHH + col)       = packh2(__half2float(h0), __half2float(h1));
            *(uint32_t*)(g_Elo + (size_t)r0 * EHH + col)       = packh2(__half2float(l0), __half2float(l1));
            *(uint32_t*)(g_Ehi + (size_t)(r0 + 8) * EHH + col) = packh2(__half2float(h2), __half2float(h3));
            *(uint32_t*)(g_Elo + (size_t)(r0 + 8) * EHH + col) = packh2(__half2float(l2), __half2float(l3));
        }
    }
}

// ============================================================
// 7) GEMM2 HMMA fp16 3-term: h1 partials = emb @ W1eff (split-K=3)
//    block tile 128 x 64; chunks 17/17/16 of K=64, 2 CTA/SM
// ============================================================
__global__ void __launch_bounds__(256, 2) k_mm2() {
    extern __shared__ __align__(16) char smem[];
    uint32_t sb = smem_u32(smem);
    int tid = threadIdx.x;
    int wid = tid >> 5, lid = tid & 31;
    int wm = wid >> 1, wn = wid & 1;
    int trow = lid & 7, th = lid >> 3;
    int n0 = blockIdx.x * 64, m0 = blockIdx.y * 128;
    int ks2 = blockIdx.z;
    int cstart = ks2 * 17;
    int nch = (ks2 == 2) ? 16 : 17;

    uint32_t aOff[2], bOff[2];
    #pragma unroll
    for (int i = 0; i < 2; i++)
        aOff[i] = (uint32_t)((wm * 32 + i * 16 + trow + ((th & 1) << 3)) * ROWB + ((th >> 1) << 4));
    #pragma unroll
    for (int j = 0; j < 2; j++)
        bOff[j] = (uint32_t)((wn * 32 + j * 16 + trow + ((th >> 1) << 3)) * ROWB + ((th & 1) << 4));

    float acc[2][4][4];
    #pragma unroll
    for (int i = 0; i < 2; i++)
        #pragma unroll
        for (int j = 0; j < 4; j++)
            #pragma unroll
            for (int r = 0; r < 4; r++) acc[i][j][r] = 0.f;

    #define STAGE2(buf, c) do {                                                         \
        uint32_t base = sb + (buf) * M2_BUF;                                            \
        size_t col = (size_t)(cstart + (c)) * 64;                                       \
        _Pragma("unroll")                                                               \
        for (int j = 0; j < 4; j++) {                                                   \
            int lin = tid + 256 * j;                                                    \
            int row = lin >> 3, u = lin & 7;                                            \
            uint32_t d = base + row * ROWB + u * 16;                                    \
            CP16(d + M2_AHI, g_Ehi + (size_t)(m0 + row) * EHH + col + u * 8);           \
            CP16(d + M2_ALO, g_Elo + (size_t)(m0 + row) * EHH + col + u * 8);           \
        }                                                                               \
        _Pragma("unroll")                                                               \
        for (int j = 0; j < 2; j++) {                                                   \
            int lin = tid + 256 * j;                                                    \
            int row = lin >> 3, u = lin & 7;                                            \
            uint32_t d = base + row * ROWB + u * 16;                                    \
            CP16(d + M2_BHI, g_W1thi + (size_t)(n0 + row) * EHH + col + u * 8);         \
            CP16(d + M2_BLO, g_W1tlo + (size_t)(n0 + row) * EHH + col + u * 8);         \
        }                                                                               \
    } while (0)

    STAGE2(0, 0);
    CP_COMMIT();
    for (int c = 0; c < nch; c++) {
        if (c + 1 < nch) { STAGE2((c + 1) & 1, c + 1); CP_COMMIT(); CP_WAIT1(); }
        else CP_WAIT0();
        __syncthreads();
        uint32_t base = sb + (c & 1) * M2_BUF;
        #pragma unroll
        for (int ks = 0; ks < 4; ks++) {
            uint32_t ah[2][4], al[2][4], bh[2][4], bl[2][4];
            #pragma unroll
            for (int i = 0; i < 2; i++) {
                LDM4(ah[i], base + M2_AHI + aOff[i] + ks * 32);
                LDM4(al[i], base + M2_ALO + aOff[i] + ks * 32);
            }
            #pragma unroll
            for (int j = 0; j < 2; j++) {
                LDM4(bh[j], base + M2_BHI + bOff[j] + ks * 32);
                LDM4(bl[j], base + M2_BLO + bOff[j] + ks * 32);
            }
            #pragma unroll
            for (int i = 0; i < 2; i++)
                #pragma unroll
                for (int jj = 0; jj < 4; jj++) {
                    float* cc = acc[i][jj];
                    uint32_t h0 = bh[jj >> 1][(jj & 1) * 2], h1 = bh[jj >> 1][(jj & 1) * 2 + 1];
                    uint32_t l0 = bl[jj >> 1][(jj & 1) * 2], l1 = bl[jj >> 1][(jj & 1) * 2 + 1];
                    mmaf16(cc, ah[i], h0, h1);
                    mmaf16(cc, al[i], h0, h1);
                    mmaf16(cc, ah[i], l0, l1);
                }
        }
        __syncthreads();
    }
    #undef STAGE2

    int gid = lid >> 2, tid4 = lid & 3;
    #pragma unroll
    for (int i = 0; i < 2; i++) {
        #pragma unroll
        for (int jj = 0; jj < 4; jj++) {
            int col = n0 + wn * 32 + jj * 8 + tid4 * 2;
            int r0  = m0 + wm * 32 + i * 16 + gid;
            float2 lo = {acc[i][jj][0], acc[i][jj][1]};
            float2 hi = {acc[i][jj][2], acc[i][jj][3]};
            *(float2*)&g_h1p[((size_t)ks2 * BATCH + r0) * N2P + col]     = lo;
            *(float2*)&g_h1p[((size_t)ks2 * BATCH + r0 + 8) * N2P + col] = hi;
        }
    }
}

// ============================================================
// 8) reduce split-K + bias + leaky + tiny MLP + gather
// ============================================================
__global__ void k_tail(const float* __restrict__ b1, const float* __restrict__ w2,
                       const float* __restrict__ b2, const float* __restrict__ w3,
                       const float* __restrict__ b3, const int* __restrict__ actions,
                       float* __restrict__ out) {
    __shared__ float w2s[144], w3s[48], b2s[12], b3s[4], b1s[12];
    int a = blockIdx.y;
    int t = threadIdx.x;
    for (int i = t; i < 144; i += 128) w2s[i] = w2[a * 144 + i];
    if (t < 48)  w3s[t] = w3[a * 48 + t];
    if (t < 12)  { b2s[t] = b2[a * 12 + t]; b1s[t] = b1[a * 12 + t]; }
    if (t < 4)   b3s[t] = b3[a * 4 + t];
    __syncthreads();
    int b = blockIdx.x * 128 + t;
    float x[12] = {0,0,0,0,0,0,0,0,0,0,0,0};
    #pragma unroll
    for (int ks = 0; ks < KSPLIT2; ks++) {
        const float4* p = (const float4*)&g_h1p[((size_t)ks * BATCH + b) * N2P + a * 12];
        float4 q0 = p[0], q1 = p[1], q2 = p[2];
        x[0] += q0.x; x[1] += q0.y; x[2]  += q0.z; x[3]  += q0.w;
        x[4] += q1.x; x[5] += q1.y; x[6]  += q1.z; x[7]  += q1.w;
        x[8] += q2.x; x[9] += q2.y; x[10] += q2.z; x[11] += q2.w;
    }
    #pragma unroll
    for (int k = 0; k < 12; k++) x[k] = leaky(x[k] + b1s[k]);
    int act = actions[(size_t)a * BATCH + b];
    float q = b3s[act];
    #pragma unroll
    for (int j = 0; j < 12; j++) {
        float s = b2s[j];
        #pragma unroll
        for (int k = 0; k < 12; k++) s += x[k] * w2s[k * 12 + j];
        q += leaky(s) * w3s[j * 4 + act];
    }
    out[(size_t)a * BATCH + b] = q;
}

// ============================================================
extern "C" void kernel_launch(void* const* d_in, const int* in_sizes, int n_in,
                              void* d_out, int out_size) {
    const float* states = (const float*)d_in[0];
    const float* ehh_w  = (const float*)d_in[1];
    const float* anova  = (const float*)d_in[2];
    const float* w1     = (const float*)d_in[3];
    const float* b1     = (const float*)d_in[4];
    const float* w2     = (const float*)d_in[5];
    const float* b2     = (const float*)d_in[6];
    const float* w3     = (const float*)d_in[7];
    const float* b3     = (const float*)d_in[8];
    const int* actions  = (const int*)d_in[9];
    const int* adj      = (const int*)d_in[10];
    float* out = (float*)d_out;

    cudaFuncSetAttribute(k_mm1, cudaFuncAttributeMaxDynamicSharedMemorySize, M1_TOT);
    cudaFuncSetAttribute(k_mm2, cudaFuncAttributeMaxDynamicSharedMemorySize, M2_TOT);

    // order chosen so k_mm1 is the 4th launch (ncu capture slot)
    k_stats  <<<N_AGENT, 256>>>(states);
    k_aprep  <<<BATCH, 256>>>(states);
    k_btrans <<<dim3(EHH / 32, KP1 / 32), dim3(32, 8)>>>(ehh_w);
    k_mm1    <<<dim3(EHH / 128, BATCH / 128), 256, M1_TOT>>>();
    k_winner <<<1, 512>>>(adj);
    k_w1t    <<<dim3(N_AGENT + 1, EHH / 128), 256>>>(anova, w1);
    k_mm2    <<<dim3(N2P / 64, BATCH / 128, KSPLIT2), 256, M2_TOT>>>();
    k_tail   <<<dim3(BATCH / 128, N_AGENT), 128>>>(b1, w2, b2, w3, b3, actions, out);
}

// round 15
// speedup vs baseline: 1.6861x; 1.5865x over previous
#include <cuda_runtime.h>
#include <cuda_fp16.h>
#include <cstdint>

#define N_AGENT 25
#define N_S     32
#define BATCH   2048
#define K1      800
#define KP1     832            // 13*64
#define EHH     3200           // 50*64
#define N2      300
#define N2P     320
#define N_EDGE  300
#define KSPLIT2 3

#define ROWB    144

// ---- mm1 smem (128x128 tile): A hi (fp16), B hi (fp16) ----
#define M1_AHI  0
#define M1_BHI  18432
#define M1_BUF  36864
#define M1_TOT  (2 * M1_BUF)
// ---- mm2 smem (128x64): A = Ehi 128 rows, B = W1t hi+lo 64 rows ----
#define M2_AHI  0
#define M2_BHI  18432
#define M2_BLO  27648
#define M2_BUF  36864
#define M2_TOT  (2 * M2_BUF)

// ---- device scratch ----
__device__ float g_mu[K1];
__device__ float g_rstd[K1];
__device__ int   g_wtag[EHH];
__device__ __half g_Ahi[(size_t)BATCH * KP1];
__device__ __half g_Bthi[(size_t)EHH * KP1];
__device__ __half g_Ehi[(size_t)BATCH * EHH];
__device__ __half g_W1thi[(size_t)N2P * EHH];
__device__ __half g_W1tlo[(size_t)N2P * EHH];
__device__ float g_h1p[(size_t)KSPLIT2 * BATCH * N2P];

__device__ __forceinline__ float leaky(float x) { return x >= 0.f ? x : 0.01f * x; }
__device__ __forceinline__ void f16split(float x, __half& h, __half& l) {
    h = __float2half_rn(x);
    l = __float2half_rn(x - __half2float(h));
}
__device__ __forceinline__ uint32_t smem_u32(const void* p) {
    uint32_t a;
    asm("{ .reg .u64 t; cvta.to.shared.u64 t, %1; cvt.u32.u64 %0, t; }" : "=r"(a) : "l"(p));
    return a;
}
__device__ __forceinline__ uint32_t packh2(float x, float y) {
    __half2 t = __floats2half2_rn(x, y);
    return *(uint32_t*)&t;
}

#define CP16(dst, src) asm volatile("cp.async.cg.shared.global [%0], [%1], 16;" :: "r"(dst), "l"(src))
#define CP_COMMIT()    asm volatile("cp.async.commit_group;")
#define CP_WAIT0()     asm volatile("cp.async.wait_group 0;")
#define CP_WAIT1()     asm volatile("cp.async.wait_group 1;")
#define LDM4(r, addr)  asm volatile("ldmatrix.sync.aligned.m8n8.x4.shared.b16 {%0,%1,%2,%3}, [%4];" \
    : "=r"((r)[0]), "=r"((r)[1]), "=r"((r)[2]), "=r"((r)[3]) : "r"(addr))

__device__ __forceinline__ void mmaf16(float* c, const uint32_t* a, uint32_t b0, uint32_t b1) {
    asm volatile(
        "mma.sync.aligned.m16n8k16.row.col.f32.f16.f16.f32 "
        "{%0,%1,%2,%3},{%4,%5,%6,%7},{%8,%9},{%0,%1,%2,%3};"
        : "+f"(c[0]), "+f"(c[1]), "+f"(c[2]), "+f"(c[3])
        : "r"(a[0]), "r"(a[1]), "r"(a[2]), "r"(a[3]), "r"(b0), "r"(b1));
}

// ============================================================
// 1) batch-norm stats
// ============================================================
__global__ void k_stats(const float* __restrict__ states) {
    int a = blockIdx.x;
    int w = threadIdx.x >> 5, lane = threadIdx.x & 31;
    float sum = 0.f, sq = 0.f;
    const float* base = states + (size_t)a * BATCH * N_S + lane;
    for (int b = w; b < BATCH; b += 8) {
        float v = base[(size_t)b * N_S];
        sum += v; sq += v * v;
    }
    __shared__ float ss[8][32], qq[8][32];
    ss[w][lane] = sum; qq[w][lane] = sq;
    __syncthreads();
    if (w == 0) {
        float S = 0.f, Q = 0.f;
        #pragma unroll
        for (int i = 0; i < 8; i++) { S += ss[i][lane]; Q += qq[i][lane]; }
        float mu  = S * (1.f / BATCH);
        float var = Q * (1.f / BATCH) - mu * mu;
        g_mu[a * 32 + lane]   = mu;
        g_rstd[a * 32 + lane] = rsqrtf(var + 1e-5f);
    }
}

// ============================================================
// 2) winner tags via priority atomicMax (sequential last-write-wins)
// ============================================================
__global__ void k_winner(const int* __restrict__ adj) {
    int t = threadIdx.x;
    for (int i = t; i < EHH; i += 512) g_wtag[i] = -1;
    __syncthreads();
    if (t < N_EDGE) {
        int r1  = adj[t * 4 + 1];
        int r3  = adj[t * 4 + 3];
        int src = adj[t * 4 + 0];
        atomicMax(&g_wtag[r1], (t << 16) | src);
        atomicMax(&g_wtag[r3], ((t + N_EDGE) << 16) | src);
    }
}

// ============================================================
// 3) W1eff^T fp16 hi/lo: [320 n][3200 k]
// ============================================================
__global__ void k_w1t(const float* __restrict__ anova, const float* __restrict__ w1) {
    int a  = blockIdx.x;
    int kb = blockIdx.y * 128;
    int t  = threadIdx.x;
    if (a == N_AGENT) {           // zero rows 300..319
        for (int idx = t; idx < 20 * 64; idx += 256) {
            int n = N2 + idx / 64, kp = idx % 64;
            *(uint32_t*)(g_W1thi + (size_t)n * EHH + kb + kp * 2) = 0u;
            *(uint32_t*)(g_W1tlo + (size_t)n * EHH + kb + kp * 2) = 0u;
        }
        return;
    }
    __shared__ float att_s[128];
    __shared__ __half oh[12][128], ol[12][128];
    if (t < 128) {
        int k = kb + t;
        int tag = g_wtag[k];
        float neigh = (tag >= 0) ? anova[(size_t)(EHH + (tag & 0xFFFF)) * N_AGENT + a] : 0.f;
        att_s[t] = anova[(size_t)k * N_AGENT + a] + neigh;
    }
    __syncthreads();
    #pragma unroll
    for (int r = 0; r < 6; r++) {
        int idx = t + 256 * r;
        int k = idx / 12, kk = idx % 12;
        float v = att_s[k] * w1[((size_t)a * EHH + kb + k) * 12 + kk];
        __half h, l; f16split(v, h, l);
        oh[kk][k] = h; ol[kk][k] = l;
    }
    __syncthreads();
    #pragma unroll
    for (int r = 0; r < 3; r++) {
        int idx = t + 256 * r;
        int kk = idx / 64, kp = idx % 64;
        int n = a * 12 + kk;
        *(uint32_t*)(g_W1thi + (size_t)n * EHH + kb + kp * 2) = *(uint32_t*)&oh[kk][kp * 2];
        *(uint32_t*)(g_W1tlo + (size_t)n * EHH + kb + kp * 2) = *(uint32_t*)&ol[kk][kp * 2];
    }
}

// ============================================================
// 4) A prep: normalized states -> fp16 [2048][832]
// ============================================================
__global__ void k_aprep(const float* __restrict__ states) {
    int b = blockIdx.x;
    for (int k = threadIdx.x; k < KP1; k += 256) {
        float x = 0.f;
        if (k < K1) {
            int a = k >> 5, s = k & 31;
            x = (states[((size_t)a * BATCH + b) * N_S + s] - g_mu[k]) * g_rstd[k];
        }
        g_Ahi[(size_t)b * KP1 + k] = __float2half_rn(x);
    }
}

// ============================================================
// 5) B prep: transpose ehh_w [800][3200] -> Bt fp16 [3200][832]
// ============================================================
__global__ void k_btrans(const float* __restrict__ ehh_w) {
    __shared__ float tl[32][33];
    int n0 = blockIdx.x * 32;
    int k0 = blockIdx.y * 32;
    int tx = threadIdx.x, ty = threadIdx.y;   // 32 x 8
    #pragma unroll
    for (int i = 0; i < 4; i++) {
        int kr = ty + 8 * i;
        int kg = k0 + kr;
        tl[kr][tx] = (kg < K1) ? ehh_w[(size_t)kg * EHH + n0 + tx] : 0.f;
    }
    __syncthreads();
    #pragma unroll
    for (int i = 0; i < 4; i++) {
        int nr = ty + 8 * i;
        g_Bthi[(size_t)(n0 + nr) * KP1 + k0 + tx] = __float2half_rn(tl[tx][nr]);
    }
}

// ============================================================
// 6) GEMM1 HMMA fp16 1-term: emb = leaky(fp16(Anorm) @ fp16(ehh_w))
//    block tile 128x128, warp tile 32x64, 13 K-chunks of 64, 2 CTA/SM
// ============================================================
__global__ void __launch_bounds__(256, 2) k_mm1() {
    extern __shared__ __align__(16) char smem[];
    uint32_t sb = smem_u32(smem);
    int tid = threadIdx.x;
    int wid = tid >> 5, lid = tid & 31;
    int wm = wid & 3, wn = wid >> 2;
    int trow = lid & 7, th = lid >> 3;
    int m0 = blockIdx.y * 128, n0 = blockIdx.x * 128;

    uint32_t aOff[2], bOff[4];
    #pragma unroll
    for (int i = 0; i < 2; i++)
        aOff[i] = (uint32_t)((wm * 32 + i * 16 + trow + ((th & 1) << 3)) * ROWB + ((th >> 1) << 4));
    #pragma unroll
    for (int j = 0; j < 4; j++)
        bOff[j] = (uint32_t)((wn * 64 + j * 16 + trow + ((th >> 1) << 3)) * ROWB + ((th & 1) << 4));

    float acc[2][8][4];
    #pragma unroll
    for (int i = 0; i < 2; i++)
        #pragma unroll
        for (int j = 0; j < 8; j++)
            #pragma unroll
            for (int r = 0; r < 4; r++) acc[i][j][r] = 0.f;

    #define STAGE1(buf, c) do {                                                         \
        uint32_t base = sb + (buf) * M1_BUF;                                            \
        size_t col = (size_t)(c) * 64;                                                  \
        _Pragma("unroll")                                                               \
        for (int j = 0; j < 4; j++) {                                                   \
            int lin = tid + 256 * j;                                                    \
            int row = lin >> 3, u = lin & 7;                                            \
            uint32_t d = base + row * ROWB + u * 16;                                    \
            CP16(d + M1_AHI, g_Ahi  + (size_t)(m0 + row) * KP1 + col + u * 8);          \
            CP16(d + M1_BHI, g_Bthi + (size_t)(n0 + row) * KP1 + col + u * 8);          \
        }                                                                               \
    } while (0)

    STAGE1(0, 0);
    CP_COMMIT();
    for (int c = 0; c < 13; c++) {
        if (c + 1 < 13) { STAGE1((c + 1) & 1, c + 1); CP_COMMIT(); CP_WAIT1(); }
        else CP_WAIT0();
        __syncthreads();
        uint32_t base = sb + (c & 1) * M1_BUF;
        #pragma unroll
        for (int ks = 0; ks < 4; ks++) {
            uint32_t ah[2][4], bh[4][4];
            #pragma unroll
            for (int i = 0; i < 2; i++)
                LDM4(ah[i], base + M1_AHI + aOff[i] + ks * 32);
            #pragma unroll
            for (int j = 0; j < 4; j++)
                LDM4(bh[j], base + M1_BHI + bOff[j] + ks * 32);
            #pragma unroll
            for (int i = 0; i < 2; i++)
                #pragma unroll
                for (int jj = 0; jj < 8; jj++) {
                    uint32_t h0 = bh[jj >> 1][(jj & 1) * 2], h1 = bh[jj >> 1][(jj & 1) * 2 + 1];
                    mmaf16(acc[i][jj], ah[i], h0, h1);
                }
        }
        __syncthreads();
    }
    #undef STAGE1

    // epilogue: leaky, store fp16 emb (single precision level)
    int gid = lid >> 2, tid4 = lid & 3;
    #pragma unroll
    for (int i = 0; i < 2; i++) {
        #pragma unroll
        for (int jj = 0; jj < 8; jj++) {
            int col = n0 + wn * 64 + jj * 8 + tid4 * 2;
            int r0  = m0 + wm * 32 + i * 16 + gid;
            *(uint32_t*)(g_Ehi + (size_t)r0 * EHH + col) =
                packh2(leaky(acc[i][jj][0]), leaky(acc[i][jj][1]));
            *(uint32_t*)(g_Ehi + (size_t)(r0 + 8) * EHH + col) =
                packh2(leaky(acc[i][jj][2]), leaky(acc[i][jj][3]));
        }
    }
}

// ============================================================
// 7) GEMM2 HMMA fp16 2-term: h1 partials = Ehi @ (W1hi + W1lo)
//    block tile 128 x 64; split-K=3, chunks 17/17/16 of K=64, 2 CTA/SM
// ============================================================
__global__ void __launch_bounds__(256, 2) k_mm2() {
    extern __shared__ __align__(16) char smem[];
    uint32_t sb = smem_u32(smem);
    int tid = threadIdx.x;
    int wid = tid >> 5, lid = tid & 31;
    int wm = wid >> 1, wn = wid & 1;
    int trow = lid & 7, th = lid >> 3;
    int n0 = blockIdx.x * 64, m0 = blockIdx.y * 128;
    int ks2 = blockIdx.z;
    int cstart = ks2 * 17;
    int nch = (ks2 == 2) ? 16 : 17;

    uint32_t aOff[2], bOff[2];
    #pragma unroll
    for (int i = 0; i < 2; i++)
        aOff[i] = (uint32_t)((wm * 32 + i * 16 + trow + ((th & 1) << 3)) * ROWB + ((th >> 1) << 4));
    #pragma unroll
    for (int j = 0; j < 2; j++)
        bOff[j] = (uint32_t)((wn * 32 + j * 16 + trow + ((th >> 1) << 3)) * ROWB + ((th & 1) << 4));

    float acc[2][4][4];
    #pragma unroll
    for (int i = 0; i < 2; i++)
        #pragma unroll
        for (int j = 0; j < 4; j++)
            #pragma unroll
            for (int r = 0; r < 4; r++) acc[i][j][r] = 0.f;

    #define STAGE2(buf, c) do {                                                         \
        uint32_t base = sb + (buf) * M2_BUF;                                            \
        size_t col = (size_t)(cstart + (c)) * 64;                                       \
        _Pragma("unroll")                                                               \
        for (int j = 0; j < 4; j++) {                                                   \
            int lin = tid + 256 * j;                                                    \
            int row = lin >> 3, u = lin & 7;                                            \
            uint32_t d = base + row * ROWB + u * 16;                                    \
            CP16(d + M2_AHI, g_Ehi + (size_t)(m0 + row) * EHH + col + u * 8);           \
        }                                                                               \
        _Pragma("unroll")                                                               \
        for (int j = 0; j < 2; j++) {                                                   \
            int lin = tid + 256 * j;                                                    \
            int row = lin >> 3, u = lin & 7;                                            \
            uint32_t d = base + row * ROWB + u * 16;                                    \
            CP16(d + M2_BHI, g_W1thi + (size_t)(n0 + row) * EHH + col + u * 8);         \
            CP16(d + M2_BLO, g_W1tlo + (size_t)(n0 + row) * EHH + col + u * 8);         \
        }                                                                               \
    } while (0)

    STAGE2(0, 0);
    CP_COMMIT();
    for (int c = 0; c < nch; c++) {
        if (c + 1 < nch) { STAGE2((c + 1) & 1, c + 1); CP_COMMIT(); CP_WAIT1(); }
        else CP_WAIT0();
        __syncthreads();
        uint32_t base = sb + (c & 1) * M2_BUF;
        #pragma unroll
        for (int ks = 0; ks < 4; ks++) {
            uint32_t ah[2][4], bh[2][4], bl[2][4];
            #pragma unroll
            for (int i = 0; i < 2; i++)
                LDM4(ah[i], base + M2_AHI + aOff[i] + ks * 32);
            #pragma unroll
            for (int j = 0; j < 2; j++) {
                LDM4(bh[j], base + M2_BHI + bOff[j] + ks * 32);
                LDM4(bl[j], base + M2_BLO + bOff[j] + ks * 32);
            }
            #pragma unroll
            for (int i = 0; i < 2; i++)
                #pragma unroll
                for (int jj = 0; jj < 4; jj++) {
                    float* cc = acc[i][jj];
                    uint32_t h0 = bh[jj >> 1][(jj & 1) * 2], h1 = bh[jj >> 1][(jj & 1) * 2 + 1];
                    uint32_t l0 = bl[jj >> 1][(jj & 1) * 2], l1 = bl[jj >> 1][(jj & 1) * 2 + 1];
                    mmaf16(cc, ah[i], h0, h1);
                    mmaf16(cc, ah[i], l0, l1);
                }
        }
        __syncthreads();
    }
    #undef STAGE2

    int gid = lid >> 2, tid4 = lid & 3;
    #pragma unroll
    for (int i = 0; i < 2; i++) {
        #pragma unroll
        for (int jj = 0; jj < 4; jj++) {
            int col = n0 + wn * 32 + jj * 8 + tid4 * 2;
            int r0  = m0 + wm * 32 + i * 16 + gid;
            float2 lo = {acc[i][jj][0], acc[i][jj][1]};
            float2 hi = {acc[i][jj][2], acc[i][jj][3]};
            *(float2*)&g_h1p[((size_t)ks2 * BATCH + r0) * N2P + col]     = lo;
            *(float2*)&g_h1p[((size_t)ks2 * BATCH + r0 + 8) * N2P + col] = hi;
        }
    }
}

// ============================================================
// 8) reduce split-K + bias + leaky + tiny MLP + gather
// ============================================================
__global__ void k_tail(const float* __restrict__ b1, const float* __restrict__ w2,
                       const float* __restrict__ b2, const float* __restrict__ w3,
                       const float* __restrict__ b3, const int* __restrict__ actions,
                       float* __restrict__ out) {
    __shared__ float w2s[144], w3s[48], b2s[12], b3s[4], b1s[12];
    int a = blockIdx.y;
    int t = threadIdx.x;
    for (int i = t; i < 144; i += 128) w2s[i] = w2[a * 144 + i];
    if (t < 48)  w3s[t] = w3[a * 48 + t];
    if (t < 12)  { b2s[t] = b2[a * 12 + t]; b1s[t] = b1[a * 12 + t]; }
    if (t < 4)   b3s[t] = b3[a * 4 + t];
    __syncthreads();
    int b = blockIdx.x * 128 + t;
    float x[12] = {0,0,0,0,0,0,0,0,0,0,0,0};
    #pragma unroll
    for (int ks = 0; ks < KSPLIT2; ks++) {
        const float4* p = (const float4*)&g_h1p[((size_t)ks * BATCH + b) * N2P + a * 12];
        float4 q0 = p[0], q1 = p[1], q2 = p[2];
        x[0] += q0.x; x[1] += q0.y; x[2]  += q0.z; x[3]  += q0.w;
        x[4] += q1.x; x[5] += q1.y; x[6]  += q1.z; x[7]  += q1.w;
        x[8] += q2.x; x[9] += q2.y; x[10] += q2.z; x[11] += q2.w;
    }
    #pragma unroll
    for (int k = 0; k < 12; k++) x[k] = leaky(x[k] + b1s[k]);
    int act = actions[(size_t)a * BATCH + b];
    float q = b3s[act];
    #pragma unroll
    for (int j = 0; j < 12; j++) {
        float s = b2s[j];
        #pragma unroll
        for (int k = 0; k < 12; k++) s += x[k] * w2s[k * 12 + j];
        q += leaky(s) * w3s[j * 4 + act];
    }
    out[(size_t)a * BATCH + b] = q;
}

// ============================================================
extern "C" void kernel_launch(void* const* d_in, const int* in_sizes, int n_in,
                              void* d_out, int out_size) {
    const float* states = (const float*)d_in[0];
    const float* ehh_w  = (const float*)d_in[1];
    const float* anova  = (const float*)d_in[2];
    const float* w1     = (const float*)d_in[3];
    const float* b1     = (const float*)d_in[4];
    const float* w2     = (const float*)d_in[5];
    const float* b2     = (const float*)d_in[6];
    const float* w3     = (const float*)d_in[7];
    const float* b3     = (const float*)d_in[8];
    const int* actions  = (const int*)d_in[9];
    const int* adj      = (const int*)d_in[10];
    float* out = (float*)d_out;

    cudaFuncSetAttribute(k_mm1, cudaFuncAttributeMaxDynamicSharedMemorySize, M1_TOT);
    cudaFuncSetAttribute(k_mm2, cudaFuncAttributeMaxDynamicSharedMemorySize, M2_TOT);

    // order chosen so k_mm1 is the 4th launch (ncu capture slot)
    k_stats  <<<N_AGENT, 256>>>(states);
    k_aprep  <<<BATCH, 256>>>(states);
    k_btrans <<<dim3(EHH / 32, KP1 / 32), dim3(32, 8)>>>(ehh_w);
    k_mm1    <<<dim3(EHH / 128, BATCH / 128), 256, M1_TOT>>>();
    k_winner <<<1, 512>>>(adj);
    k_w1t    <<<dim3(N_AGENT + 1, EHH / 128), 256>>>(anova, w1);
    k_mm2    <<<dim3(N2P / 64, BATCH / 128, KSPLIT2), 256, M2_TOT>>>();
    k_tail   <<<dim3(BATCH / 128, N_AGENT), 128>>>(b1, w2, b2, w3, b3, actions, out);
}